// round 13
// baseline (speedup 1.0000x reference)
#include <cuda_runtime.h>
#include <cuda_fp16.h>
#include <cuda.h>
#include <cstdint>
#include <math.h>

#define S_LEN 2048
#define Bsz   32
#define Hdim  512
#define K2    1024      // 2H
#define WSTRIDE 2048    // 4H (W row stride)

#define KCH   64        // K per chunk (64 fp16 = 128B rows, SW128)
#define NCH   16        // K2 / KCH
#define A_ST  16384     // 128 rows * 128B fp16
#define B_ST  32768     // 256 rows * 128B fp16
#define DSMEM_BYTES (2*A_ST + 2*B_ST + 1024)   // 99328 -> 2 CTAs/SM

#define NTHR  320       // warps 0-7 loaders, warp 8 issuer, warp 9 B producer + spiller

// arch-feature gate: tcgen05 only exists in the sm_103a pass
#if defined(__CUDA_ARCH__) && defined(__CUDA_ARCH_FEAT_SM103_ALL)
#define TCGEN_OK 1
#else
#define TCGEN_OK 0
#endif

// idesc kind::f16 SS: dtype=f32(1)<<4, atype=fp16(0), btype=fp16(0), N=256 -> 32<<17, M=128 -> 8<<24
#define IDESC_F16 ((1u<<4) | (32u<<17) | (8u<<24))

// ---------------- scratch (device globals; no allocation allowed) ----------
__device__ float  g_u_part[8 * Bsz * Hdim];
__device__ float  g_u[Bsz * Hdim];
__device__ __half g_w2h[Hdim * K2];                // W2 in fp16, K-major [512,1024]
// enc in fp16, SW128-swizzled stage layout: [tile 512][chunk 16][16384 B]
__device__ uint8_t g_ench_sw[(size_t)512 * 16 * 16384];
__device__ float  g_scores_part[2 * Bsz * S_LEN];  // [n_half][b*S+s]
__device__ float  g_attn[Bsz * S_LEN];
__device__ float  g_ctx_part[512 * K2];            // per-tile context partials

// ---------------- PTX helpers ------------------------------------------------
__device__ __forceinline__ uint32_t smem_u32(const void* p) {
    uint32_t a;
    asm("{ .reg .u64 t; cvta.to.shared.u64 t, %1; cvt.u32.u64 %0, t; }" : "=r"(a) : "l"(p));
    return a;
}

__device__ __forceinline__ uint32_t pack_f16x2(float lo, float hi) {
    uint32_t r;
    asm("cvt.rn.f16x2.f32 %0, %1, %2;" : "=r"(r) : "f"(hi), "f"(lo));
    return r;
}

#define MBAR_INIT(addr, cnt) \
    asm volatile("mbarrier.init.shared.b64 [%0], %1;" :: "r"(addr), "r"(cnt) : "memory")
#define MBAR_EXPECT_TX(addr, bytes) \
    asm volatile("mbarrier.arrive.expect_tx.shared.b64 _, [%0], %1;" :: "r"(addr), "r"(bytes) : "memory")
#define MBAR_ARRIVE(addr) \
    asm volatile("mbarrier.arrive.shared.b64 _, [%0];" :: "r"(addr) : "memory")

#define MBAR_WAIT(addr, parity) do { \
    asm volatile( \
        "{\n\t.reg .pred P1;\n\t" \
        "WL_%=:\n\t" \
        "mbarrier.try_wait.parity.acquire.cta.shared::cta.b64 P1, [%0], %1, 0x989680;\n\t" \
        "@P1 bra.uni WD_%=;\n\t" \
        "bra.uni WL_%=;\n\t" \
        "WD_%=:\n\t}" \
        :: "r"(addr), "r"(parity) : "memory"); \
} while (0)

#define TMA_LOAD_2D(dst, tmap, x, y, mbar) \
    asm volatile( \
        "cp.async.bulk.tensor.2d.shared::cta.global.tile.mbarrier::complete_tx::bytes " \
        "[%0], [%1, {%2, %3}], [%4];" \
        :: "r"(dst), "l"(tmap), "r"(x), "r"(y), "r"(mbar) : "memory")

// bulk SMEM -> GMEM copy (sm_90+)
#define BULK_S2G(gdst, ssrc, bytes) \
    asm volatile("cp.async.bulk.global.shared::cta.bulk_group [%0], [%1], %2;" \
        :: "l"(gdst), "r"(ssrc), "r"(bytes) : "memory")
#define BULK_COMMIT() asm volatile("cp.async.bulk.commit_group;" ::: "memory")
#define BULK_WAIT0()  asm volatile("cp.async.bulk.wait_group 0;" ::: "memory")

#define FENCE_ASYNC() asm volatile("fence.proxy.async.shared::cta;" ::: "memory")

#if TCGEN_OK
#define TCGEN05_ALLOC(slot, ncols) \
    asm volatile("tcgen05.alloc.cta_group::1.sync.aligned.shared::cta.b32 [%0], %1;" \
        :: "r"(slot), "r"(ncols) : "memory")
#define TCGEN05_RELINQ() \
    asm volatile("tcgen05.relinquish_alloc_permit.cta_group::1.sync.aligned;")
#define TCGEN05_DEALLOC(base, ncols) \
    asm volatile("tcgen05.dealloc.cta_group::1.sync.aligned.b32 %0, %1;" :: "r"(base), "r"(ncols))
#define TCGEN05_COMMIT(mbar) \
    asm volatile("tcgen05.commit.cta_group::1.mbarrier::arrive::one.shared::cluster.b64 [%0];" \
        :: "r"(mbar) : "memory")
#define TCGEN05_FENCE_AFTER() \
    asm volatile("tcgen05.fence::after_thread_sync;" ::: "memory")
#define TCGEN05_WAIT_LD() \
    asm volatile("tcgen05.wait::ld.sync.aligned;" ::: "memory")

__device__ __forceinline__ void mma_f16(uint32_t d_tmem, uint64_t adesc, uint64_t bdesc,
                                        uint32_t idesc, uint32_t enable) {
    uint32_t zero = 0;
    asm volatile(
        "{\n\t.reg .pred p;\n\t"
        "setp.ne.u32 p, %6, 0;\n\t"
        "tcgen05.mma.cta_group::1.kind::f16 [%0], %1, %2, %3, {%4, %4, %4, %4}, p;\n\t}"
        :: "r"(d_tmem), "l"(adesc), "l"(bdesc), "r"(idesc), "r"(zero), "r"(zero), "r"(enable)
        : "memory");
}

// SW128, Blackwell v1, SBO=64, LBO=1 (K-major, 128B rows)
__device__ __forceinline__ uint64_t make_desc(uint32_t addr) {
    const uint64_t base =
        (uint64_t(2) << 61) | (uint64_t(1) << 46) | (uint64_t(64) << 32) | (uint64_t(1) << 16);
    return base | ((uint64_t)(addr >> 4) & 0x3FFF);
}

#define LDTM_X32(r, addr) \
    asm volatile( \
        "tcgen05.ld.sync.aligned.32x32b.x32.b32 " \
        "{%0,%1,%2,%3,%4,%5,%6,%7,%8,%9,%10,%11,%12,%13,%14,%15," \
        "%16,%17,%18,%19,%20,%21,%22,%23,%24,%25,%26,%27,%28,%29,%30,%31}, [%32];" \
        : "=r"((r)[0]),"=r"((r)[1]),"=r"((r)[2]),"=r"((r)[3]), \
          "=r"((r)[4]),"=r"((r)[5]),"=r"((r)[6]),"=r"((r)[7]), \
          "=r"((r)[8]),"=r"((r)[9]),"=r"((r)[10]),"=r"((r)[11]), \
          "=r"((r)[12]),"=r"((r)[13]),"=r"((r)[14]),"=r"((r)[15]), \
          "=r"((r)[16]),"=r"((r)[17]),"=r"((r)[18]),"=r"((r)[19]), \
          "=r"((r)[20]),"=r"((r)[21]),"=r"((r)[22]),"=r"((r)[23]), \
          "=r"((r)[24]),"=r"((r)[25]),"=r"((r)[26]),"=r"((r)[27]), \
          "=r"((r)[28]),"=r"((r)[29]),"=r"((r)[30]),"=r"((r)[31]) \
        : "r"(addr))
#endif // TCGEN_OK

// ---------------- W2 fp32 -> fp16 (once). grid 512, 256 thr ----------------
__global__ void conv_w_kernel(const float* __restrict__ W) {
    int i = (blockIdx.x * 256 + threadIdx.x) * 4;
    int row = i >> 10, col = i & 1023;
    float4 w4 = *reinterpret_cast<const float4*>(W + (size_t)row * WSTRIDE + K2 + col);
    uint2 h;
    h.x = pack_f16x2(w4.x, w4.y);
    h.y = pack_f16x2(w4.z, w4.w);
    *reinterpret_cast<uint2*>(g_w2h + i) = h;
}

// ---------------- phase 1: u = W1 * hidden (K-split) -----------------------
__global__ void phase1_kernel(const float* __restrict__ hidden,
                              const float* __restrict__ W) {
    __shared__ float hid_s[Bsz][132];
    const int h0 = blockIdx.x * 128;
    const int k0 = blockIdx.y * 128;
    const int t  = threadIdx.x;

    #pragma unroll
    for (int p = 0; p < 4; p++) {
        int lin = p * 256 + t;
        int b = lin >> 5;
        int kq = lin & 31;
        float4 v4 = *reinterpret_cast<const float4*>(hidden + (size_t)b * K2 + k0 + kq * 4);
        *reinterpret_cast<float4*>(&hid_s[b][kq * 4]) = v4;
    }
    __syncthreads();

    const int h  = h0 + (t >> 1);
    const int b0 = (t & 1) * 16;
    float acc[16];
    #pragma unroll
    for (int i = 0; i < 16; i++) acc[i] = 0.f;

    const float* wrow = W + (size_t)h * WSTRIDE + k0;
    for (int k = 0; k < 128; k += 4) {
        float4 w4 = *reinterpret_cast<const float4*>(wrow + k);
        #pragma unroll
        for (int bb = 0; bb < 16; bb++) {
            float4 h4 = *reinterpret_cast<const float4*>(&hid_s[b0 + bb][k]);
            acc[bb] += w4.x * h4.x + w4.y * h4.y + w4.z * h4.z + w4.w * h4.w;
        }
    }
    float* up = g_u_part + (size_t)blockIdx.y * (Bsz * Hdim);
    #pragma unroll
    for (int bb = 0; bb < 16; bb++) up[(size_t)(b0 + bb) * Hdim + h] = acc[bb];
}

__global__ void phase1b_kernel(const float* __restrict__ bias) {
    int idx = blockIdx.x * 256 + threadIdx.x;
    float s = bias[idx & (Hdim - 1)];
    #pragma unroll
    for (int p = 0; p < 8; p++) s += g_u_part[p * (Bsz * Hdim) + idx];
    g_u[idx] = s;
}

__device__ __forceinline__ float fast_tanh(float x) {
    float e = __expf(2.f * x);
    return 1.f - __fdividef(2.f, e + 1.f);
}

// ---------------- phase 2: warp-specialized fp16 tcgen05 GEMM --------------
// grid (2, 512): x = n-half (256 cols), y = 128-row m-tile. 320 threads.
// 2 CTAs/SM. warp 9 doubles as B producer + A-stage spiller (bulk SMEM->GMEM).
__global__ void __launch_bounds__(NTHR, 2)
phase2_kernel(const __grid_constant__ CUtensorMap tma_b,
              const float* __restrict__ enc,
              const float* __restrict__ v) {
    extern __shared__ char dyn[];
    __shared__ __align__(16) uint64_t mbar_afull[2];
    __shared__ __align__(16) uint64_t mbar_adone[2];
    __shared__ __align__(16) uint64_t mbar_aspill[2];
    __shared__ __align__(16) uint64_t mbar_bfull[2];
    __shared__ __align__(16) uint64_t mbar_bdone[2];
    __shared__ __align__(16) uint64_t mbar_final;
    __shared__ uint32_t tmem_slot;
    __shared__ float sp2[2][128];

    const int t    = threadIdx.x;
    const int wid  = t >> 5;
    const int lane = t & 31;
    const int n0   = blockIdx.x * 256;
    const int m0   = blockIdx.y * 128;   // global row (b*2048 + s0)
    const int b    = m0 >> 11;

    uint32_t dbase = smem_u32(dyn);
    dbase = (dbase + 1023u) & ~1023u;    // SW128 atom alignment (1024B) — load-bearing
    char* dynA = (char*)dyn + (dbase - smem_u32(dyn));
    const uint32_t Abase = dbase;                 // 2 x 16KB
    const uint32_t Bbase = dbase + 2 * A_ST;      // 2 x 32KB

#if TCGEN_OK
    if (wid == 0) {
        TCGEN05_ALLOC(smem_u32(&tmem_slot), 256);
        TCGEN05_RELINQ();
    }
    if (t == 0) {
        MBAR_INIT(smem_u32(&mbar_afull[0]), 256);
        MBAR_INIT(smem_u32(&mbar_afull[1]), 256);
        MBAR_INIT(smem_u32(&mbar_adone[0]), 1);
        MBAR_INIT(smem_u32(&mbar_adone[1]), 1);
        MBAR_INIT(smem_u32(&mbar_aspill[0]), 1);
        MBAR_INIT(smem_u32(&mbar_aspill[1]), 1);
        MBAR_INIT(smem_u32(&mbar_bfull[0]), 1);
        MBAR_INIT(smem_u32(&mbar_bfull[1]), 1);
        MBAR_INIT(smem_u32(&mbar_bdone[0]), 1);
        MBAR_INIT(smem_u32(&mbar_bdone[1]), 1);
        MBAR_INIT(smem_u32(&mbar_final), 1);
    }
    __syncthreads();
    const uint32_t tmem = tmem_slot;

    if (t < 256) {
        // ---------------- A loaders (warps 0-7), coalesced ------------------
        // pass p (0..7): row = p*16 + wid*2 + (lane>>4), col4 = lane&15.
        const int rbase = wid * 2 + (lane >> 4);       // 0..15
        const int col4  = lane & 15;                   // float4 index in chunk row
        const float* aptr = enc + (size_t)(m0 + rbase) * K2 + col4 * 4;
        const uint32_t swc = (uint32_t)rbase * 128 +
                             (uint32_t)((col4 * 8) ^ ((rbase & 7) << 4));

        float4 ra[8];
        #pragma unroll
        for (int p = 0; p < 8; p++)
            ra[p] = *reinterpret_cast<const float4*>(aptr + (size_t)p * 16 * K2);

        for (int i = 0; i < NCH; i++) {
            const int ab = i & 1;
            if (i >= 2) {
                MBAR_WAIT(smem_u32(&mbar_adone[ab]),  ((i - 2) >> 1) & 1);
                MBAR_WAIT(smem_u32(&mbar_aspill[ab]), ((i - 2) >> 1) & 1);
            }
            char* abuf = dynA + ab * A_ST;
            #pragma unroll
            for (int p = 0; p < 8; p++) {
                uint2 u;
                u.x = pack_f16x2(ra[p].x, ra[p].y);
                u.y = pack_f16x2(ra[p].z, ra[p].w);
                *reinterpret_cast<uint2*>(abuf + swc + (uint32_t)p * 2048) = u;
            }
            FENCE_ASYNC();
            MBAR_ARRIVE(smem_u32(&mbar_afull[ab]));
            if (i + 1 < NCH) {
                #pragma unroll
                for (int p = 0; p < 8; p++)
                    ra[p] = *reinterpret_cast<const float4*>(
                        aptr + (size_t)p * 16 * K2 + (i + 1) * KCH);
            }
        }
    } else if (t == 256) {
        // ---------------- MMA issuer (warp 8) -------------------------------
        for (int i = 0; i < NCH; i++) {
            const int ab = i & 1;
            MBAR_WAIT(smem_u32(&mbar_afull[ab]), (i >> 1) & 1);
            MBAR_WAIT(smem_u32(&mbar_bfull[ab]), (i >> 1) & 1);
            const uint64_t adesc = make_desc(Abase + (uint32_t)ab * A_ST);
            const uint64_t bdesc = make_desc(Bbase + (uint32_t)ab * B_ST);
            #pragma unroll
            for (int ks = 0; ks < 4; ks++) {
                mma_f16(tmem, adesc + ks * 2, bdesc + ks * 2,
                        IDESC_F16, (i > 0 || ks > 0) ? 1u : 0u);
            }
            TCGEN05_COMMIT(smem_u32(&mbar_adone[ab]));
            TCGEN05_COMMIT(smem_u32(&mbar_bdone[ab]));
        }
        TCGEN05_COMMIT(smem_u32(&mbar_final));
    } else if (t == 288) {
        // ------------ B TMA producer + A-stage spiller (warp 9) -------------
        uint8_t* gench = g_ench_sw + (size_t)blockIdx.y * (NCH * A_ST);
        const bool spill = (n0 == 0);
        for (int j = 0; j < NCH; j++) {
            const int bb = j & 1;
            if (j >= 2) MBAR_WAIT(smem_u32(&mbar_bdone[bb]), ((j - 2) >> 1) & 1);
            uint32_t mb = smem_u32(&mbar_bfull[bb]);
            MBAR_EXPECT_TX(mb, B_ST);
            TMA_LOAD_2D(Bbase + (uint32_t)bb * B_ST, &tma_b, j * KCH, n0, mb);
            // spill A stage j after loaders fill it (overlaps chunk-j MMAs)
            MBAR_WAIT(smem_u32(&mbar_afull[bb]), (j >> 1) & 1);
            if (spill) {
                BULK_S2G(gench + (size_t)j * A_ST, Abase + (uint32_t)bb * A_ST, A_ST);
                BULK_COMMIT();
                BULK_WAIT0();
            }
            MBAR_ARRIVE(smem_u32(&mbar_aspill[bb]));
        }
    }

    // ---------------- epilogue ----------------------------------------------
    MBAR_WAIT(smem_u32(&mbar_final), 0);
    TCGEN05_FENCE_AFTER();

    // stage u,v into (now free) A region
    float* us = reinterpret_cast<float*>(dynA);
    float* vs = us + 256;
    for (int j = t; j < 256; j += NTHR) {
        us[j] = g_u[(size_t)b * Hdim + n0 + j];
        vs[j] = v[n0 + j];
    }
    __syncthreads();

    if (wid < 8) {   // warp w -> rows (w&3)*32+lane, cols (w>>2)*128 + [0,128)
        const int half = wid >> 2;
        const int colbase = half * 128;
        const int row = (wid & 3) * 32 + lane;
        float acc = 0.f;
        #pragma unroll
        for (int c = 0; c < 4; c++) {
            uint32_t r[32];
            LDTM_X32(r, tmem + colbase + c * 32);
            TCGEN05_WAIT_LD();
            #pragma unroll
            for (int j = 0; j < 32; j++) {
                const int col = colbase + c * 32 + j;
                acc += fast_tanh(__uint_as_float(r[j]) + us[col]) * vs[col];
            }
        }
        sp2[half][row] = acc;
    }
    __syncthreads();
    if (t < 128)
        g_scores_part[(size_t)blockIdx.x * (Bsz * S_LEN) + m0 + t] =
            sp2[0][t] + sp2[1][t];
    __syncthreads();
    if (wid == 0) TCGEN05_DEALLOC(tmem, 256);

#else
    // ---- never-executed correctness fallback (plain sm_103 pass) ----------
    (void)tmem_slot; (void)sp2; (void)dynA; (void)Abase; (void)Bbase;
    (void)mbar_afull; (void)mbar_adone; (void)mbar_aspill;
    (void)mbar_bfull; (void)mbar_bdone; (void)mbar_final; (void)wid; (void)lane;
    if (t < 128) {
        const int r = m0 + t;
        float s = 0.f;
        for (int h = n0; h < n0 + 256; h++) {
            float e = g_u[(size_t)b * Hdim + h];
            const __half* wr = g_w2h + (size_t)h * K2;
            for (int k = 0; k < K2; k++)
                e += enc[(size_t)r * K2 + k] * __half2float(wr[k]);
            s += tanhf(e) * v[h];
        }
        g_scores_part[(size_t)blockIdx.x * (Bsz * S_LEN) + r] = s;
        // fallback also populates swizzled fp16 enc for the context kernel
        if (blockIdx.x == 0) {
            uint8_t* base = g_ench_sw + (size_t)blockIdx.y * (NCH * A_ST);
            for (int k = 0; k < K2; k++) {
                int ch = k >> 6, c = k & 63;
                uint32_t off = (uint32_t)ch * A_ST + (uint32_t)t * 128 +
                               (uint32_t)((c * 2) ^ ((t & 7) << 4));
                *reinterpret_cast<__half*>(base + off) =
                    __float2half(enc[(size_t)r * K2 + k]);
            }
        }
    }
#endif
}

// ---------------- phase 3: softmax over S per batch. grid 32, 512 thr ------
__global__ void __launch_bounds__(512)
softmax_kernel() {
    __shared__ float red[16];
    const int b = blockIdx.x, t = threadIdx.x;
    const int wid = t >> 5, lane = t & 31;
    const int base = b * S_LEN;

    float4 a = *reinterpret_cast<const float4*>(&g_scores_part[base + t * 4]);
    float4 c = *reinterpret_cast<const float4*>(&g_scores_part[Bsz * S_LEN + base + t * 4]);
    float v0 = a.x + c.x, v1 = a.y + c.y, v2 = a.z + c.z, v3 = a.w + c.w;

    float mx = fmaxf(fmaxf(v0, v1), fmaxf(v2, v3));
    #pragma unroll
    for (int o = 16; o > 0; o >>= 1) mx = fmaxf(mx, __shfl_xor_sync(~0u, mx, o));
    if (lane == 0) red[wid] = mx;
    __syncthreads();
    if (t < 16) {
        float m = red[t];
        #pragma unroll
        for (int o = 8; o > 0; o >>= 1) m = fmaxf(m, __shfl_xor_sync(0xffffu, m, o));
        red[t] = m;
    }
    __syncthreads();
    mx = red[0];

    float e0 = __expf(v0 - mx), e1 = __expf(v1 - mx);
    float e2 = __expf(v2 - mx), e3 = __expf(v3 - mx);
    float sum = e0 + e1 + e2 + e3;
    #pragma unroll
    for (int o = 16; o > 0; o >>= 1) sum += __shfl_xor_sync(~0u, sum, o);
    __syncthreads();
    if (lane == 0) red[wid] = sum;
    __syncthreads();
    if (t < 16) {
        float s = red[t];
        #pragma unroll
        for (int o = 8; o > 0; o >>= 1) s += __shfl_xor_sync(0xffffu, s, o);
        red[t] = s;
    }
    __syncthreads();
    const float inv = 1.f / red[0];

    float4 o4 = {e0 * inv, e1 * inv, e2 * inv, e3 * inv};
    *reinterpret_cast<float4*>(&g_attn[base + t * 4]) = o4;
}

// ---------------- phase 4: context from swizzled fp16 enc ------------------
// grid 512 (one CTA per 128-row m-tile), 256 thr:
// thread t -> chunk t>>4, uint2 index t&15; reduces 128 rows.
__global__ void __launch_bounds__(256)
context_kernel() {
    __shared__ float a_s[128];
    const int tile = blockIdx.x;
    const int t = threadIdx.x;
    const int m0 = tile * 128;
    const int b  = m0 >> 11;
    if (t < 128) a_s[t] = g_attn[(size_t)b * S_LEN + (m0 & (S_LEN - 1)) + t];
    __syncthreads();

    const int chunk = t >> 4;
    const int c4 = t & 15;
    const uint8_t* base = g_ench_sw + ((size_t)tile * NCH + chunk) * A_ST;
    float4 acc = {0.f, 0.f, 0.f, 0.f};
    #pragma unroll 4
    for (int r = 0; r < 128; r++) {
        uint2 h = *reinterpret_cast<const uint2*>(
            base + r * 128 + ((c4 * 8) ^ ((r & 7) << 4)));
        float a = a_s[r];
        float2 e0 = __half22float2(*reinterpret_cast<const __half2*>(&h.x));
        float2 e1 = __half22float2(*reinterpret_cast<const __half2*>(&h.y));
        acc.x += a * e0.x; acc.y += a * e0.y;
        acc.z += a * e1.x; acc.w += a * e1.y;
    }
    const int k = chunk * 64 + c4 * 4;
    *reinterpret_cast<float4*>(g_ctx_part + (size_t)tile * K2 + k) = acc;
}

// reduce 16 tile-partials per batch -> d_out. grid 32, 256 thr
__global__ void context_reduce_kernel(float* __restrict__ out) {
    const int b = blockIdx.x, t = threadIdx.x;
    float4 s = {0.f, 0.f, 0.f, 0.f};
    #pragma unroll
    for (int c = 0; c < 16; c++) {
        float4 p = *reinterpret_cast<const float4*>(
            g_ctx_part + ((size_t)(b * 16 + c)) * K2 + t * 4);
        s.x += p.x; s.y += p.y; s.z += p.z; s.w += p.w;
    }
    *reinterpret_cast<float4*>(out + (size_t)b * K2 + t * 4) = s;
}

// ---------------- host: tensormap build + launch ----------------------------
typedef CUresult (*PFN_encodeTiled)(
    CUtensorMap*, CUtensorMapDataType, cuuint32_t, void*,
    const cuuint64_t*, const cuuint64_t*, const cuuint32_t*, const cuuint32_t*,
    CUtensorMapInterleave, CUtensorMapSwizzle, CUtensorMapL2promotion,
    CUtensorMapFloatOOBfill);

extern "C" void kernel_launch(void* const* d_in, const int* in_sizes, int n_in,
                              void* d_out, int out_size) {
    const float* hidden = (const float*)d_in[0];   // [32, 1024]
    const float* enc    = (const float*)d_in[1];   // [32, 2048, 1024]
    const float* W      = (const float*)d_in[2];   // [512, 2048]
    const float* bias   = (const float*)d_in[3];   // [512]
    const float* v      = (const float*)d_in[4];   // [512]
    float* out = (float*)d_out;                    // [32, 1024]

    void* fn = nullptr;
    cudaDriverEntryPointQueryResult qr;
    cudaGetDriverEntryPoint("cuTensorMapEncodeTiled", &fn, cudaEnableDefault, &qr);
    PFN_encodeTiled encode = (PFN_encodeTiled)fn;

    void* w2h_ptr = nullptr;
    cudaGetSymbolAddress(&w2h_ptr, g_w2h);

    CUtensorMap tma_b;
    {
        // g_w2h as 2D fp16 [1024 cols, 512 rows], box [64, 256], SW128
        cuuint64_t dims[2]    = {(cuuint64_t)K2, (cuuint64_t)Hdim};
        cuuint64_t strides[1] = {(cuuint64_t)K2 * sizeof(__half)};
        cuuint32_t box[2]     = {KCH, 256};
        cuuint32_t estr[2]    = {1, 1};
        encode(&tma_b, CU_TENSOR_MAP_DATA_TYPE_FLOAT16, 2, w2h_ptr,
               dims, strides, box, estr,
               CU_TENSOR_MAP_INTERLEAVE_NONE, CU_TENSOR_MAP_SWIZZLE_128B,
               CU_TENSOR_MAP_L2_PROMOTION_L2_128B, CU_TENSOR_MAP_FLOAT_OOB_FILL_NONE);
    }

    cudaFuncSetAttribute(phase2_kernel, cudaFuncAttributeMaxDynamicSharedMemorySize,
                         DSMEM_BYTES);

    conv_w_kernel<<<512, 256>>>(W);
    phase1_kernel<<<dim3(4, 8), 256>>>(hidden, W);
    phase1b_kernel<<<64, 256>>>(bias);
    phase2_kernel<<<dim3(2, 512), NTHR, DSMEM_BYTES>>>(tma_b, enc, v);
    softmax_kernel<<<32, 512>>>();
    context_kernel<<<512, 256>>>();
    context_reduce_kernel<<<32, 256>>>(out);
}

// round 14
// speedup vs baseline: 1.0393x; 1.0393x over previous
#include <cuda_runtime.h>
#include <cuda_fp16.h>
#include <cuda.h>
#include <cstdint>
#include <math.h>

#define S_LEN 2048
#define Bsz   32
#define Hdim  512
#define K2    1024      // 2H
#define WSTRIDE 2048    // 4H (W row stride)

#define KCH   64        // K per chunk (64 fp16 = 128B rows, SW128)
#define NCH   16        // K2 / KCH
#define A_TILE 16384    // 128 rows * 128B fp16 (one m-tile)
#define A_ST  32768     // 2 m-tiles per stage
#define B_ST  32768     // 256 rows * 128B fp16
#define NSTG  3         // ring depth for both A and B
#define DSMEM_BYTES (NSTG*A_ST + NSTG*B_ST + 1024)   // 197632 -> 1 CTA/SM

#define NTHR  320       // warps 0-7 loaders, warp 8 issuer, warp 9 producer

// arch-feature gate: tcgen05 only exists in the sm_103a pass
#if defined(__CUDA_ARCH__) && defined(__CUDA_ARCH_FEAT_SM103_ALL)
#define TCGEN_OK 1
#else
#define TCGEN_OK 0
#endif

// idesc kind::f16 SS: dtype=f32(1)<<4, fp16 in, N=256 -> 32<<17, M=128 -> 8<<24
#define IDESC_F16 ((1u<<4) | (32u<<17) | (8u<<24))

// ---------------- scratch (device globals; no allocation allowed) ----------
__device__ float  g_u_part[8 * Bsz * Hdim];
__device__ float  g_u[Bsz * Hdim];
__device__ __half g_w2h[Hdim * K2];                // W2 in fp16, K-major [512,1024]
__device__ float  g_scores_part[2 * Bsz * S_LEN];  // [n_half][b*S+s]
__device__ float  g_attn[Bsz * S_LEN];
__device__ float  g_ctx_part[32 * Bsz * K2];

// ---------------- PTX helpers ------------------------------------------------
__device__ __forceinline__ uint32_t smem_u32(const void* p) {
    uint32_t a;
    asm("{ .reg .u64 t; cvta.to.shared.u64 t, %1; cvt.u32.u64 %0, t; }" : "=r"(a) : "l"(p));
    return a;
}

__device__ __forceinline__ uint32_t pack_f16x2(float lo, float hi) {
    uint32_t r;
    asm("cvt.rn.f16x2.f32 %0, %1, %2;" : "=r"(r) : "f"(hi), "f"(lo));
    return r;
}

#define MBAR_INIT(addr, cnt) \
    asm volatile("mbarrier.init.shared.b64 [%0], %1;" :: "r"(addr), "r"(cnt) : "memory")
#define MBAR_EXPECT_TX(addr, bytes) \
    asm volatile("mbarrier.arrive.expect_tx.shared.b64 _, [%0], %1;" :: "r"(addr), "r"(bytes) : "memory")
#define MBAR_ARRIVE(addr) \
    asm volatile("mbarrier.arrive.shared.b64 _, [%0];" :: "r"(addr) : "memory")

#define MBAR_WAIT(addr, parity) do { \
    asm volatile( \
        "{\n\t.reg .pred P1;\n\t" \
        "WL_%=:\n\t" \
        "mbarrier.try_wait.parity.acquire.cta.shared::cta.b64 P1, [%0], %1, 0x989680;\n\t" \
        "@P1 bra.uni WD_%=;\n\t" \
        "bra.uni WL_%=;\n\t" \
        "WD_%=:\n\t}" \
        :: "r"(addr), "r"(parity) : "memory"); \
} while (0)

#define TMA_LOAD_2D(dst, tmap, x, y, mbar) \
    asm volatile( \
        "cp.async.bulk.tensor.2d.shared::cta.global.tile.mbarrier::complete_tx::bytes " \
        "[%0], [%1, {%2, %3}], [%4];" \
        :: "r"(dst), "l"(tmap), "r"(x), "r"(y), "r"(mbar) : "memory")

#define FENCE_ASYNC() asm volatile("fence.proxy.async.shared::cta;" ::: "memory")

#if TCGEN_OK
#define TCGEN05_ALLOC(slot, ncols) \
    asm volatile("tcgen05.alloc.cta_group::1.sync.aligned.shared::cta.b32 [%0], %1;" \
        :: "r"(slot), "r"(ncols) : "memory")
#define TCGEN05_RELINQ() \
    asm volatile("tcgen05.relinquish_alloc_permit.cta_group::1.sync.aligned;")
#define TCGEN05_DEALLOC(base, ncols) \
    asm volatile("tcgen05.dealloc.cta_group::1.sync.aligned.b32 %0, %1;" :: "r"(base), "r"(ncols))
#define TCGEN05_COMMIT(mbar) \
    asm volatile("tcgen05.commit.cta_group::1.mbarrier::arrive::one.shared::cluster.b64 [%0];" \
        :: "r"(mbar) : "memory")
#define TCGEN05_FENCE_AFTER() \
    asm volatile("tcgen05.fence::after_thread_sync;" ::: "memory")
#define TCGEN05_WAIT_LD() \
    asm volatile("tcgen05.wait::ld.sync.aligned;" ::: "memory")

__device__ __forceinline__ void mma_f16(uint32_t d_tmem, uint64_t adesc, uint64_t bdesc,
                                        uint32_t idesc, uint32_t enable) {
    uint32_t zero = 0;
    asm volatile(
        "{\n\t.reg .pred p;\n\t"
        "setp.ne.u32 p, %6, 0;\n\t"
        "tcgen05.mma.cta_group::1.kind::f16 [%0], %1, %2, %3, {%4, %4, %4, %4}, p;\n\t}"
        :: "r"(d_tmem), "l"(adesc), "l"(bdesc), "r"(idesc), "r"(zero), "r"(zero), "r"(enable)
        : "memory");
}

// SW128, Blackwell v1, SBO=64, LBO=1 (K-major, 128B rows)
__device__ __forceinline__ uint64_t make_desc(uint32_t addr) {
    const uint64_t base =
        (uint64_t(2) << 61) | (uint64_t(1) << 46) | (uint64_t(64) << 32) | (uint64_t(1) << 16);
    return base | ((uint64_t)(addr >> 4) & 0x3FFF);
}

#define LDTM_X32(r, addr) \
    asm volatile( \
        "tcgen05.ld.sync.aligned.32x32b.x32.b32 " \
        "{%0,%1,%2,%3,%4,%5,%6,%7,%8,%9,%10,%11,%12,%13,%14,%15," \
        "%16,%17,%18,%19,%20,%21,%22,%23,%24,%25,%26,%27,%28,%29,%30,%31}, [%32];" \
        : "=r"((r)[0]),"=r"((r)[1]),"=r"((r)[2]),"=r"((r)[3]), \
          "=r"((r)[4]),"=r"((r)[5]),"=r"((r)[6]),"=r"((r)[7]), \
          "=r"((r)[8]),"=r"((r)[9]),"=r"((r)[10]),"=r"((r)[11]), \
          "=r"((r)[12]),"=r"((r)[13]),"=r"((r)[14]),"=r"((r)[15]), \
          "=r"((r)[16]),"=r"((r)[17]),"=r"((r)[18]),"=r"((r)[19]), \
          "=r"((r)[20]),"=r"((r)[21]),"=r"((r)[22]),"=r"((r)[23]), \
          "=r"((r)[24]),"=r"((r)[25]),"=r"((r)[26]),"=r"((r)[27]), \
          "=r"((r)[28]),"=r"((r)[29]),"=r"((r)[30]),"=r"((r)[31]) \
        : "r"(addr))
#endif // TCGEN_OK

// ---------------- W2 fp32 -> fp16 (once). grid 512, 256 thr ----------------
__global__ void conv_w_kernel(const float* __restrict__ W) {
    int i = (blockIdx.x * 256 + threadIdx.x) * 4;
    int row = i >> 10, col = i & 1023;
    float4 w4 = *reinterpret_cast<const float4*>(W + (size_t)row * WSTRIDE + K2 + col);
    uint2 h;
    h.x = pack_f16x2(w4.x, w4.y);
    h.y = pack_f16x2(w4.z, w4.w);
    *reinterpret_cast<uint2*>(g_w2h + i) = h;
}

// ---------------- phase 1: u = W1 * hidden (K-split) -----------------------
__global__ void phase1_kernel(const float* __restrict__ hidden,
                              const float* __restrict__ W) {
    __shared__ float hid_s[Bsz][132];
    const int h0 = blockIdx.x * 128;
    const int k0 = blockIdx.y * 128;
    const int t  = threadIdx.x;

    #pragma unroll
    for (int p = 0; p < 4; p++) {
        int lin = p * 256 + t;
        int b = lin >> 5;
        int kq = lin & 31;
        float4 v4 = *reinterpret_cast<const float4*>(hidden + (size_t)b * K2 + k0 + kq * 4);
        *reinterpret_cast<float4*>(&hid_s[b][kq * 4]) = v4;
    }
    __syncthreads();

    const int h  = h0 + (t >> 1);
    const int b0 = (t & 1) * 16;
    float acc[16];
    #pragma unroll
    for (int i = 0; i < 16; i++) acc[i] = 0.f;

    const float* wrow = W + (size_t)h * WSTRIDE + k0;
    for (int k = 0; k < 128; k += 4) {
        float4 w4 = *reinterpret_cast<const float4*>(wrow + k);
        #pragma unroll
        for (int bb = 0; bb < 16; bb++) {
            float4 h4 = *reinterpret_cast<const float4*>(&hid_s[b0 + bb][k]);
            acc[bb] += w4.x * h4.x + w4.y * h4.y + w4.z * h4.z + w4.w * h4.w;
        }
    }
    float* up = g_u_part + (size_t)blockIdx.y * (Bsz * Hdim);
    #pragma unroll
    for (int bb = 0; bb < 16; bb++) up[(size_t)(b0 + bb) * Hdim + h] = acc[bb];
}

__global__ void phase1b_kernel(const float* __restrict__ bias) {
    int idx = blockIdx.x * 256 + threadIdx.x;
    float s = bias[idx & (Hdim - 1)];
    #pragma unroll
    for (int p = 0; p < 8; p++) s += g_u_part[p * (Bsz * Hdim) + idx];
    g_u[idx] = s;
}

__device__ __forceinline__ float fast_tanh(float x) {
    float e = __expf(2.f * x);
    return 1.f - __fdividef(2.f, e + 1.f);
}

// ---------------- phase 2: warp-specialized fp16 tcgen05 GEMM --------------
// grid (2, 256): x = n-half (256 cols), y = 256-row m-PAIR (2 tiles).
// 320 threads, 1 CTA/SM, A/B rings depth 3. Each B chunk feeds 2 m-tiles
// (8 MMA dispatches) -> B L2 traffic halved vs R11.
__global__ void __launch_bounds__(NTHR, 1)
phase2_kernel(const __grid_constant__ CUtensorMap tma_b,
              const float* __restrict__ enc,
              const float* __restrict__ v) {
    extern __shared__ char dyn[];
    __shared__ __align__(16) uint64_t mbar_afull[NSTG];
    __shared__ __align__(16) uint64_t mbar_adone[NSTG];
    __shared__ __align__(16) uint64_t mbar_bfull[NSTG];
    __shared__ __align__(16) uint64_t mbar_bdone[NSTG];
    __shared__ __align__(16) uint64_t mbar_final;
    __shared__ uint32_t tmem_slot;

    const int t    = threadIdx.x;
    const int wid  = t >> 5;
    const int lane = t & 31;
    const int n0   = blockIdx.x * 256;
    const int m0   = blockIdx.y * 256;   // global row (b*2048 + s0), 256-row pair
    const int b    = m0 >> 11;

    uint32_t dbase = smem_u32(dyn);
    dbase = (dbase + 1023u) & ~1023u;    // SW128 atom alignment (1024B) — load-bearing
    char* dynA = (char*)dyn + (dbase - smem_u32(dyn));
    const uint32_t Abase = dbase;                   // 3 x 32KB (2 tiles/stage)
    const uint32_t Bbase = dbase + NSTG * A_ST;     // 3 x 32KB

#if TCGEN_OK
    if (wid == 0) {
        TCGEN05_ALLOC(smem_u32(&tmem_slot), 512);
        TCGEN05_RELINQ();
    }
    if (t == 0) {
        #pragma unroll
        for (int s = 0; s < NSTG; s++) {
            MBAR_INIT(smem_u32(&mbar_afull[s]), 256);
            MBAR_INIT(smem_u32(&mbar_adone[s]), 1);
            MBAR_INIT(smem_u32(&mbar_bfull[s]), 1);
            MBAR_INIT(smem_u32(&mbar_bdone[s]), 1);
        }
        MBAR_INIT(smem_u32(&mbar_final), 1);
    }
    __syncthreads();
    const uint32_t tmem = tmem_slot;

    if (t < 256) {
        // -------- A loaders (warps 0-7): 256 rows per chunk, coalesced ------
        // pass p (0..15): row = p*16 + wid*2 + (lane>>4); tile = p>=8.
        const int rbase = wid * 2 + (lane >> 4);       // 0..15
        const int col4  = lane & 15;                   // float4 index in chunk row
        const float* aptr = enc + (size_t)(m0 + rbase) * K2 + col4 * 4;
        const uint32_t swc = (uint32_t)rbase * 128 +
                             (uint32_t)((col4 * 8) ^ ((rbase & 7) << 4));

        float4 ra[16];
        #pragma unroll
        for (int p = 0; p < 16; p++)
            ra[p] = *reinterpret_cast<const float4*>(aptr + (size_t)p * 16 * K2);

        for (int i = 0; i < NCH; i++) {
            const int ab = i % NSTG;
            if (i >= NSTG) MBAR_WAIT(smem_u32(&mbar_adone[ab]), ((i - NSTG) / NSTG) & 1);
            char* abuf = dynA + ab * A_ST;
            #pragma unroll
            for (int p = 0; p < 16; p++) {
                uint2 u;
                u.x = pack_f16x2(ra[p].x, ra[p].y);
                u.y = pack_f16x2(ra[p].z, ra[p].w);
                *reinterpret_cast<uint2*>(abuf + ((p >= 8) ? A_TILE : 0) +
                                          (uint32_t)(p & 7) * 2048 + swc) = u;
            }
            FENCE_ASYNC();
            MBAR_ARRIVE(smem_u32(&mbar_afull[ab]));
            if (i + 1 < NCH) {
                #pragma unroll
                for (int p = 0; p < 16; p++)
                    ra[p] = *reinterpret_cast<const float4*>(
                        aptr + (size_t)p * 16 * K2 + (i + 1) * KCH);
            }
        }
    } else if (t == 256) {
        // ---------------- MMA issuer (warp 8): 8 dispatches/chunk -----------
        for (int i = 0; i < NCH; i++) {
            const int ab = i % NSTG;
            const uint32_t ph = (uint32_t)((i / NSTG) & 1);
            MBAR_WAIT(smem_u32(&mbar_afull[ab]), ph);
            MBAR_WAIT(smem_u32(&mbar_bfull[ab]), ph);
            const uint64_t adesc0 = make_desc(Abase + (uint32_t)ab * A_ST);
            const uint64_t adesc1 = make_desc(Abase + (uint32_t)ab * A_ST + A_TILE);
            const uint64_t bdesc  = make_desc(Bbase + (uint32_t)ab * B_ST);
            #pragma unroll
            for (int ks = 0; ks < 4; ks++)
                mma_f16(tmem, adesc0 + ks * 2, bdesc + ks * 2,
                        IDESC_F16, (i > 0 || ks > 0) ? 1u : 0u);
            #pragma unroll
            for (int ks = 0; ks < 4; ks++)
                mma_f16(tmem + 256, adesc1 + ks * 2, bdesc + ks * 2,
                        IDESC_F16, (i > 0 || ks > 0) ? 1u : 0u);
            TCGEN05_COMMIT(smem_u32(&mbar_adone[ab]));
            TCGEN05_COMMIT(smem_u32(&mbar_bdone[ab]));
        }
        TCGEN05_COMMIT(smem_u32(&mbar_final));
    } else if (t == 288) {
        // ---------------- B TMA producer (warp 9), ring 3 -------------------
        for (int j = 0; j < NCH; j++) {
            const int bb = j % NSTG;
            if (j >= NSTG) MBAR_WAIT(smem_u32(&mbar_bdone[bb]), ((j - NSTG) / NSTG) & 1);
            uint32_t mb = smem_u32(&mbar_bfull[bb]);
            MBAR_EXPECT_TX(mb, B_ST);
            TMA_LOAD_2D(Bbase + (uint32_t)bb * B_ST, &tma_b, j * KCH, n0, mb);
        }
    }

    // ---------------- epilogue ----------------------------------------------
    MBAR_WAIT(smem_u32(&mbar_final), 0);
    TCGEN05_FENCE_AFTER();

    // stage u,v (n-half) into now-free A region
    float* us = reinterpret_cast<float*>(dynA);
    float* vs = us + 256;
    for (int j = t; j < 256; j += NTHR) {
        us[j] = g_u[(size_t)b * Hdim + n0 + j];
        vs[j] = v[n0 + j];
    }
    __syncthreads();

    if (wid < 8) {
        // warp w -> tile w>>2, rows (w&3)*32+lane of that tile, all 256 cols
        const int tile = wid >> 2;
        const int row  = (wid & 3) * 32 + lane;
        const uint32_t dbase_t = tmem + tile * 256;
        float acc = 0.f;
        #pragma unroll
        for (int c = 0; c < 8; c++) {
            uint32_t r[32];
            LDTM_X32(r, dbase_t + c * 32);
            TCGEN05_WAIT_LD();
            #pragma unroll
            for (int j = 0; j < 32; j++) {
                const int col = c * 32 + j;
                acc += fast_tanh(__uint_as_float(r[j]) + us[col]) * vs[col];
            }
        }
        g_scores_part[(size_t)blockIdx.x * (Bsz * S_LEN) + m0 + tile * 128 + row] = acc;
    }
    __syncthreads();
    if (wid == 0) TCGEN05_DEALLOC(tmem, 512);

#else
    // ---- never-executed correctness fallback (plain sm_103 pass) ----------
    (void)tmem_slot; (void)dynA; (void)Abase; (void)Bbase;
    (void)mbar_afull; (void)mbar_adone; (void)mbar_bfull; (void)mbar_bdone;
    (void)mbar_final; (void)wid; (void)lane;
    if (t < 256) {
        const int r = m0 + t;
        float s = 0.f;
        for (int h = n0; h < n0 + 256; h++) {
            float e = g_u[(size_t)b * Hdim + h];
            const __half* wr = g_w2h + (size_t)h * K2;
            for (int k = 0; k < K2; k++)
                e += enc[(size_t)r * K2 + k] * __half2float(wr[k]);
            s += tanhf(e) * v[h];
        }
        g_scores_part[(size_t)blockIdx.x * (Bsz * S_LEN) + r] = s;
    }
#endif
}

// ---------------- phase 3: softmax over S per batch. grid 32, 512 thr ------
__global__ void __launch_bounds__(512)
softmax_kernel() {
    __shared__ float red[16];
    const int b = blockIdx.x, t = threadIdx.x;
    const int wid = t >> 5, lane = t & 31;
    const int base = b * S_LEN;

    float4 a = *reinterpret_cast<const float4*>(&g_scores_part[base + t * 4]);
    float4 c = *reinterpret_cast<const float4*>(&g_scores_part[Bsz * S_LEN + base + t * 4]);
    float v0 = a.x + c.x, v1 = a.y + c.y, v2 = a.z + c.z, v3 = a.w + c.w;

    float mx = fmaxf(fmaxf(v0, v1), fmaxf(v2, v3));
    #pragma unroll
    for (int o = 16; o > 0; o >>= 1) mx = fmaxf(mx, __shfl_xor_sync(~0u, mx, o));
    if (lane == 0) red[wid] = mx;
    __syncthreads();
    if (t < 16) {
        float m = red[t];
        #pragma unroll
        for (int o = 8; o > 0; o >>= 1) m = fmaxf(m, __shfl_xor_sync(0xffffu, m, o));
        red[t] = m;
    }
    __syncthreads();
    mx = red[0];

    float e0 = __expf(v0 - mx), e1 = __expf(v1 - mx);
    float e2 = __expf(v2 - mx), e3 = __expf(v3 - mx);
    float sum = e0 + e1 + e2 + e3;
    #pragma unroll
    for (int o = 16; o > 0; o >>= 1) sum += __shfl_xor_sync(~0u, sum, o);
    __syncthreads();
    if (lane == 0) red[wid] = sum;
    __syncthreads();
    if (t < 16) {
        float s = red[t];
        #pragma unroll
        for (int o = 8; o > 0; o >>= 1) s += __shfl_xor_sync(0xffffu, s, o);
        red[t] = s;
    }
    __syncthreads();
    const float inv = 1.f / red[0];

    float4 o4 = {e0 * inv, e1 * inv, e2 * inv, e3 * inv};
    *reinterpret_cast<float4*>(&g_attn[base + t * 4]) = o4;
}

// ---------------- phase 4: context partials. grid (32, 32), 256 thr --------
__global__ void context_kernel(const float* __restrict__ enc) {
    __shared__ float a_s[64];
    const int chunk = blockIdx.x, b = blockIdx.y, t = threadIdx.x;
    const int s0 = chunk * 64;
    if (t < 64) a_s[t] = g_attn[b * S_LEN + s0 + t];
    __syncthreads();

    float4 acc = {0.f, 0.f, 0.f, 0.f};
    const float4* ep = reinterpret_cast<const float4*>(
        enc + ((size_t)(b * S_LEN + s0)) * K2) + t;
    #pragma unroll 8
    for (int ss = 0; ss < 64; ss++) {
        float a = a_s[ss];
        float4 e = ep[(size_t)ss * (K2 / 4)];
        acc.x += a * e.x; acc.y += a * e.y; acc.z += a * e.z; acc.w += a * e.w;
    }
    reinterpret_cast<float4*>(g_ctx_part + ((size_t)(chunk * Bsz + b)) * K2)[t] = acc;
}

__global__ void context_reduce_kernel(float* __restrict__ out) {
    const int b = blockIdx.x, t = threadIdx.x;
    float4 s = {0.f, 0.f, 0.f, 0.f};
    #pragma unroll
    for (int c = 0; c < 32; c++) {
        float4 p = reinterpret_cast<const float4*>(
            g_ctx_part + ((size_t)(c * Bsz + b)) * K2)[t];
        s.x += p.x; s.y += p.y; s.z += p.z; s.w += p.w;
    }
    reinterpret_cast<float4*>(out + (size_t)b * K2)[t] = s;
}

// ---------------- host: tensormap build + launch ----------------------------
typedef CUresult (*PFN_encodeTiled)(
    CUtensorMap*, CUtensorMapDataType, cuuint32_t, void*,
    const cuuint64_t*, const cuuint64_t*, const cuuint32_t*, const cuuint32_t*,
    CUtensorMapInterleave, CUtensorMapSwizzle, CUtensorMapL2promotion,
    CUtensorMapFloatOOBfill);

extern "C" void kernel_launch(void* const* d_in, const int* in_sizes, int n_in,
                              void* d_out, int out_size) {
    const float* hidden = (const float*)d_in[0];   // [32, 1024]
    const float* enc    = (const float*)d_in[1];   // [32, 2048, 1024]
    const float* W      = (const float*)d_in[2];   // [512, 2048]
    const float* bias   = (const float*)d_in[3];   // [512]
    const float* v      = (const float*)d_in[4];   // [512]
    float* out = (float*)d_out;                    // [32, 1024]

    void* fn = nullptr;
    cudaDriverEntryPointQueryResult qr;
    cudaGetDriverEntryPoint("cuTensorMapEncodeTiled", &fn, cudaEnableDefault, &qr);
    PFN_encodeTiled encode = (PFN_encodeTiled)fn;

    void* w2h_ptr = nullptr;
    cudaGetSymbolAddress(&w2h_ptr, g_w2h);

    CUtensorMap tma_b;
    {
        // g_w2h as 2D fp16 [1024 cols, 512 rows], box [64, 256], SW128
        cuuint64_t dims[2]    = {(cuuint64_t)K2, (cuuint64_t)Hdim};
        cuuint64_t strides[1] = {(cuuint64_t)K2 * sizeof(__half)};
        cuuint32_t box[2]     = {KCH, 256};
        cuuint32_t estr[2]    = {1, 1};
        encode(&tma_b, CU_TENSOR_MAP_DATA_TYPE_FLOAT16, 2, w2h_ptr,
               dims, strides, box, estr,
               CU_TENSOR_MAP_INTERLEAVE_NONE, CU_TENSOR_MAP_SWIZZLE_128B,
               CU_TENSOR_MAP_L2_PROMOTION_L2_128B, CU_TENSOR_MAP_FLOAT_OOB_FILL_NONE);
    }

    cudaFuncSetAttribute(phase2_kernel, cudaFuncAttributeMaxDynamicSharedMemorySize,
                         DSMEM_BYTES);

    conv_w_kernel<<<512, 256>>>(W);
    phase1_kernel<<<dim3(4, 8), 256>>>(hidden, W);
    phase1b_kernel<<<64, 256>>>(bias);
    phase2_kernel<<<dim3(2, 256), NTHR, DSMEM_BYTES>>>(tma_b, enc, v);
    softmax_kernel<<<32, 512>>>();
    context_kernel<<<dim3(32, 32), 256>>>(enc);
    context_reduce_kernel<<<32, 256>>>(out);
}